// round 4
// baseline (speedup 1.0000x reference)
#include <cuda_runtime.h>
#include <cstdint>

#define Bb   4
#define Nn   2048
#define Hh   8
#define IN_D 128
#define Oo   32
#define LOG2E 1.44269504f

#define BI   64           // rows per CTA (MMA M)
#define KC   16           // j per chunk (MMA K per chunk)
#define NCH  (Nn/KC)      // 128 chunks

// ---------------- scratch (device globals) ----------------------------------
__device__ float g_Wh[(size_t)Bb*Hh*Nn*Oo];   // [b][h][n][o], tf32-rounded
__device__ float g_asrc[(size_t)Bb*Hh*Nn];
__device__ float g_adst[(size_t)Bb*Hh*Nn];
__device__ float g_maxd[Bb*Hh];

__device__ __forceinline__ float ex2f_fast(float x) {
    float r; asm("ex2.approx.ftz.f32 %0, %1;" : "=f"(r) : "f"(x)); return r;
}
__device__ __forceinline__ float tf32_rn(float x) {
    uint32_t r; asm("cvt.rna.tf32.f32 %0, %1;" : "=r"(r) : "f"(x));
    return __uint_as_float(r);
}
__device__ __forceinline__ void cp_async16(uint32_t dst, const void* src) {
    asm volatile("cp.async.cg.shared.global [%0], [%1], 16;"
                 :: "r"(dst), "l"(src));
}

// ============================================================================
// Kernel 1: Wh (tf32-rounded, [b][h][n][o]) + alpha_src/alpha_dst
// grid (Nn/32, Hh, Bb) = 2048 CTAs, 256 threads, ONE head per CTA.
// ============================================================================
__global__ __launch_bounds__(256, 4) void wh_kernel(
    const float* __restrict__ x, const float* __restrict__ W,
    const float* __restrict__ a_src, const float* __restrict__ a_dst)
{
    __shared__ __align__(16) float x_sm[32][IN_D];      // 16 KB
    __shared__ __align__(16) float w_sm[IN_D * Oo];     // 16 KB

    const int b   = blockIdx.z;
    const int h   = blockIdx.y;
    const int n0  = blockIdx.x * 32;
    const int tid = threadIdx.x;
    const int lane = tid & 31;       // = o
    const int wq   = tid >> 5;       // warp -> 4 rows

    {   // x tile: 32*128 floats
        const float4* xg = (const float4*)(x + ((size_t)b*Nn + n0)*IN_D);
        float4* xs = (float4*)&x_sm[0][0];
        #pragma unroll
        for (int k = 0; k < 4; ++k) xs[tid + k*256] = xg[tid + k*256];
    }
    {   // W[h]: 128*32 floats
        const float4* wg = (const float4*)(W + (size_t)h*IN_D*Oo);
        float4* ws = (float4*)w_sm;
        #pragma unroll
        for (int k = 0; k < 4; ++k) ws[tid + k*256] = wg[tid + k*256];
    }
    __syncthreads();

    float acc[4] = {0.f, 0.f, 0.f, 0.f};
    #pragma unroll 8
    for (int f4 = 0; f4 < IN_D/4; ++f4) {
        float4 xv[4];
        #pragma unroll
        for (int r = 0; r < 4; ++r)
            xv[r] = ((const float4*)&x_sm[wq*4 + r][0])[f4];
        #pragma unroll
        for (int u = 0; u < 4; ++u) {
            float wv = w_sm[(f4*4 + u)*Oo + lane];
            acc[0] += (u==0?xv[0].x:u==1?xv[0].y:u==2?xv[0].z:xv[0].w) * wv;
            acc[1] += (u==0?xv[1].x:u==1?xv[1].y:u==2?xv[1].z:xv[1].w) * wv;
            acc[2] += (u==0?xv[2].x:u==1?xv[2].y:u==2?xv[2].z:xv[2].w) * wv;
            acc[3] += (u==0?xv[3].x:u==1?xv[3].y:u==2?xv[3].z:xv[3].w) * wv;
        }
    }

    const float asv = a_src[h*Oo + lane];
    const float adv = a_dst[h*Oo + lane];
    #pragma unroll
    for (int r = 0; r < 4; ++r) {
        int n = n0 + wq*4 + r;
        g_Wh[(((size_t)b*Hh + h)*Nn + n)*Oo + lane] = tf32_rn(acc[r]);
        float ps = acc[r] * asv;
        float pd = acc[r] * adv;
        #pragma unroll
        for (int s = 16; s > 0; s >>= 1) {
            ps += __shfl_xor_sync(~0u, ps, s);
            pd += __shfl_xor_sync(~0u, pd, s);
        }
        if (lane == 0) {
            g_asrc[((size_t)b*Hh + h)*Nn + n] = ps;
            g_adst[((size_t)b*Hh + h)*Nn + n] = pd;
        }
    }
}

// ============================================================================
// Kernel 2: per-(b,h) max of alpha_dst
// ============================================================================
__global__ __launch_bounds__(256) void maxd_kernel()
{
    const int bh  = blockIdx.x;
    const int tid = threadIdx.x;
    float m = -1e30f;
    for (int n = tid; n < Nn; n += 256)
        m = fmaxf(m, g_adst[(size_t)bh*Nn + n]);
    __shared__ float red[256];
    red[tid] = m;
    __syncthreads();
    for (int s = 128; s > 0; s >>= 1) {
        if (tid < s) red[tid] = fmaxf(red[tid], red[tid + s]);
        __syncthreads();
    }
    if (tid == 0) g_maxd[bh] = red[0];
}

// ============================================================================
// Kernel 3: fused masked-softmax + AV via mma.sync.m16n8k8.tf32
// grid (Nn/BI=32, Bb=4) = 128 CTAs; 512 threads (16 warps, 4/SMSP).
// Warp w: head hm = w>>1, row-half mh = w&1 (32 rows each).
// p-gen: thread -> row ith = tid>>3, j-pair j8 = tid&7.
// SMEM (dynamic, 86016 B):
//   p_sm  [8][64][20]     words 0..10239
//   wh_sm [2][8][16][40]  words 10240..20479  (cp.async double buffer)
//   ej_sm [2][8][16][2]   words 20480..20991
//   z_sm  [8][64]         words 20992..21503
// ============================================================================
__global__ __launch_bounds__(512, 1) void gat_mma(const float* __restrict__ adj,
                                                  float* __restrict__ out)
{
    extern __shared__ float sm[];
    float* p_sm  = sm;
    float* wh_sm = sm + 10240;
    float* ej_sm = sm + 20480;
    float* z_sm  = sm + 20992;

    const int tid  = threadIdx.x;
    const int lane = tid & 31;
    const int wid  = tid >> 5;       // 0..15
    const int hm   = wid >> 1;       // mma head
    const int mh   = wid & 1;        // row half (0: rows 0-31, 1: rows 32-63)
    const int b    = blockIdx.y;
    const int i0   = blockIdx.x * BI;
    const int ith  = tid >> 3;       // p-gen row 0..63
    const int j8   = tid & 7;        // p-gen j-pair (j = 2*j8, 2*j8+1)
    const int iglob = i0 + ith;
    const int g  = lane >> 2;
    const int t4 = lane & 3;

    const uint32_t wh_u32 =
        (uint32_t)__cvta_generic_to_shared(wh_sm);

    // per-(h,i) hoisted exponentials: w = max(E1i*E1j, E2i*E2j) * mask
    float E1i[Hh], E2i[Hh], zacc[Hh];
    #pragma unroll
    for (int h = 0; h < Hh; ++h) {
        float s  = g_asrc[((size_t)(b*Hh + h))*Nn + iglob];
        float md = g_maxd[b*Hh + h];
        float t  = s + md;
        float m  = fmaxf(t, 0.2f*t);                 // lrelu monotone -> row max
        E1i[h] = ex2f_fast((s - m)*LOG2E);
        E2i[h] = ex2f_fast((0.2f*s - m)*LOG2E);
        zacc[h] = 0.f;
    }

    const float2* arow  = (const float2*)(adj + ((size_t)b*Nn + iglob)*Nn);
    const float*  whg   = g_Wh + (size_t)b*Hh*Nn*Oo;
    const float*  adstb = g_adst + (size_t)b*Hh*Nn;

    // ---- prologue: cp.async wh chunk 0 -> buf 0; ej chunk 0; adj chunk 0 ----
    #pragma unroll
    for (int r = 0; r < 2; ++r) {
        int q = tid + r*512;                 // 0..1023
        int h = q >> 7, k = (q >> 3) & 15, ng = q & 7;
        cp_async16(wh_u32 + (uint32_t)(h*640 + k*40 + ng*4)*4u,
                   whg + ((size_t)h*Nn + k)*Oo + ng*4);
    }
    asm volatile("cp.async.commit_group;" ::: "memory");

    if (tid < 128) {
        int h = tid >> 4, j = tid & 15;
        float dl = adstb[(size_t)h*Nn + j] * LOG2E;
        ej_sm[h*32 + j*2 + 0] = ex2f_fast(dl);
        ej_sm[h*32 + j*2 + 1] = ex2f_fast(0.2f*dl);
    }
    float2 adjv = arow[j8];

    float acc[2][4][4];
    #pragma unroll
    for (int m = 0; m < 2; ++m)
        #pragma unroll
        for (int nt = 0; nt < 4; ++nt)
            #pragma unroll
            for (int r = 0; r < 4; ++r) acc[m][nt][r] = 0.f;

    __syncthreads();    // ej_sm[0] visible

    for (int c = 0; c < NCH; ++c) {
        const int buf = c & 1;

        // ---- issue cp.async for chunk c+1 into buf^1 ----
        if (c + 1 < NCH) {
            #pragma unroll
            for (int r = 0; r < 2; ++r) {
                int q = tid + r*512;
                int h = q >> 7, k = (q >> 3) & 15, ng = q & 7;
                cp_async16(wh_u32 + (uint32_t)((buf^1)*5120 + h*640 + k*40 + ng*4)*4u,
                           whg + ((size_t)h*Nn + (c+1)*KC + k)*Oo + ng*4);
            }
            asm volatile("cp.async.commit_group;" ::: "memory");
        }
        // ---- ej prefetch (c+1) into regs ----
        float e1n = 0.f, e2n = 0.f;
        if (c + 1 < NCH && tid < 128) {
            int h = tid >> 4, j = tid & 15;
            float dl = adstb[(size_t)h*Nn + (c+1)*KC + j] * LOG2E;
            e1n = ex2f_fast(dl);
            e2n = ex2f_fast(0.2f*dl);
        }

        // ---- mask (shared across heads) ----
        const int jb = c*KC + j8*2;
        const float m0 = (adjv.x > 0.f || jb     == iglob) ? 1.f : 0.f;
        const float m1 = (adjv.y > 0.f || jb + 1 == iglob) ? 1.f : 0.f;

        // ---- p-gen: 8 heads x 2 j ----
        #pragma unroll
        for (int h = 0; h < Hh; ++h) {
            float4 e = *(const float4*)(ej_sm + buf*256 + h*32 + j8*4);
            float w0 = fmaxf(E1i[h]*e.x, E2i[h]*e.y) * m0;
            float w1 = fmaxf(E1i[h]*e.z, E2i[h]*e.w) * m1;
            w0 = tf32_rn(w0);
            w1 = tf32_rn(w1);
            zacc[h] += w0 + w1;
            *(float2*)(p_sm + h*1280 + ith*20 + j8*2) = make_float2(w0, w1);
        }

        // ---- wait for wh[buf] ----
        if (c + 1 < NCH) asm volatile("cp.async.wait_group 1;" ::: "memory");
        else             asm volatile("cp.async.wait_group 0;" ::: "memory");
        __syncthreads();          // p ready; wh[buf] ready

        // ---- mma: warp (hm, mh) ----
        {
            const float* ph = p_sm + hm*1280 + mh*640;
            const float* wt = wh_sm + buf*5120 + hm*640;
            #pragma unroll
            for (int ks = 0; ks < 2; ++ks) {
                const int k0 = ks*8;
                uint32_t bf[4][2];
                #pragma unroll
                for (int nt = 0; nt < 4; ++nt) {
                    bf[nt][0] = __float_as_uint(wt[(k0 + t4)*40 + nt*8 + g]);
                    bf[nt][1] = __float_as_uint(wt[(k0 + t4 + 4)*40 + nt*8 + g]);
                }
                #pragma unroll
                for (int m = 0; m < 2; ++m) {
                    const float* pa = ph + (m*16 + g)*20 + k0;
                    uint32_t a0 = __float_as_uint(pa[t4]);
                    uint32_t a1 = __float_as_uint(pa[160 + t4]);
                    uint32_t a2 = __float_as_uint(pa[t4 + 4]);
                    uint32_t a3 = __float_as_uint(pa[160 + t4 + 4]);
                    #pragma unroll
                    for (int nt = 0; nt < 4; ++nt) {
                        asm volatile(
                          "mma.sync.aligned.m16n8k8.row.col.f32.tf32.tf32.f32 "
                          "{%0,%1,%2,%3}, {%4,%5,%6,%7}, {%8,%9}, {%0,%1,%2,%3};"
                          : "+f"(acc[m][nt][0]), "+f"(acc[m][nt][1]),
                            "+f"(acc[m][nt][2]), "+f"(acc[m][nt][3])
                          : "r"(a0), "r"(a1), "r"(a2), "r"(a3),
                            "r"(bf[nt][0]), "r"(bf[nt][1]));
                    }
                }
            }
        }

        // ---- prefetch adj (c+1); stage ej (c+1) ----
        if (c + 1 < NCH) {
            adjv = arow[(c+1)*8 + j8];
            if (tid < 128) {
                int h = tid >> 4, j = tid & 15;
                ej_sm[(buf^1)*256 + h*32 + j*2 + 0] = e1n;
                ej_sm[(buf^1)*256 + h*32 + j*2 + 1] = e2n;
            }
        }
        __syncthreads();          // p consumed; next ej visible
    }

    // ---- Z reduction across the 8 j8-lanes of each row ----
    #pragma unroll
    for (int h = 0; h < Hh; ++h) {
        float z = zacc[h];
        z += __shfl_xor_sync(~0u, z, 1);
        z += __shfl_xor_sync(~0u, z, 2);
        z += __shfl_xor_sync(~0u, z, 4);
        if (j8 == 0) z_sm[h*64 + ith] = z;
    }
    __syncthreads();

    // ---- epilogue: normalize, relu, store ----
    {
        float* ob = out + ((size_t)b*Nn + i0 + mh*32)*(Hh*Oo) + hm*Oo;
        #pragma unroll
        for (int m = 0; m < 2; ++m) {
            int r0 = m*16 + g;
            float zi0 = 1.f / z_sm[hm*64 + mh*32 + r0];
            float zi1 = 1.f / z_sm[hm*64 + mh*32 + r0 + 8];
            #pragma unroll
            for (int nt = 0; nt < 4; ++nt) {
                int o = nt*8 + 2*t4;
                float2 v0, v1;
                v0.x = fmaxf(acc[m][nt][0]*zi0, 0.f);
                v0.y = fmaxf(acc[m][nt][1]*zi0, 0.f);
                v1.x = fmaxf(acc[m][nt][2]*zi1, 0.f);
                v1.y = fmaxf(acc[m][nt][3]*zi1, 0.f);
                *(float2*)(ob + (size_t)r0*(Hh*Oo) + o)       = v0;
                *(float2*)(ob + (size_t)(r0 + 8)*(Hh*Oo) + o) = v1;
            }
        }
    }
}

// ============================================================================
extern "C" void kernel_launch(void* const* d_in, const int* in_sizes, int n_in,
                              void* d_out, int out_size)
{
    (void)in_sizes; (void)n_in; (void)out_size;
    const float* x     = (const float*)d_in[0];
    const float* adj   = (const float*)d_in[1];
    const float* W     = (const float*)d_in[2];
    const float* a_src = (const float*)d_in[3];
    const float* a_dst = (const float*)d_in[4];
    float* out = (float*)d_out;

    wh_kernel<<<dim3(Nn/32, Hh, Bb), 256>>>(x, W, a_src, a_dst);
    maxd_kernel<<<Bb*Hh, 256>>>();

    static const int smem_bytes = 86016;
    cudaFuncSetAttribute(gat_mma, cudaFuncAttributeMaxDynamicSharedMemorySize,
                         smem_bytes);
    gat_mma<<<dim3(Nn/BI, Bb), 512, smem_bytes>>>(adj, out);
}

// round 5
// speedup vs baseline: 1.0052x; 1.0052x over previous
#include <cuda_runtime.h>
#include <cstdint>

#define Bb   4
#define Nn   2048
#define Hh   8
#define IN_D 128
#define Oo   32
#define LOG2E 1.44269504f

#define BI   64           // rows per CTA (MMA M)
#define KC   16           // j per chunk (MMA K per chunk)
#define NCH  (Nn/KC)      // 128 chunks

// ---------------- scratch (device globals) ----------------------------------
__device__ float g_Wh[(size_t)Bb*Hh*Nn*Oo];   // [b][h][n][o], tf32-rounded
__device__ float g_asrc[(size_t)Bb*Hh*Nn];
__device__ float g_adst[(size_t)Bb*Hh*Nn];
__device__ float g_maxd[Bb*Hh];

__device__ __forceinline__ float ex2f_fast(float x) {
    float r; asm("ex2.approx.ftz.f32 %0, %1;" : "=f"(r) : "f"(x)); return r;
}
__device__ __forceinline__ float tf32_rn(float x) {
    uint32_t r; asm("cvt.rna.tf32.f32 %0, %1;" : "=r"(r) : "f"(x));
    return __uint_as_float(r);
}
__device__ __forceinline__ void cp_async16(uint32_t dst, const void* src) {
    asm volatile("cp.async.cg.shared.global [%0], [%1], 16;"
                 :: "r"(dst), "l"(src));
}

// ============================================================================
// Kernel 1: Wh (tf32-rounded, [b][h][n][o]) + alpha_src/alpha_dst
// grid (Nn/32, Hh, Bb) = 2048 CTAs, 256 threads, ONE head per CTA.
// ============================================================================
__global__ __launch_bounds__(256, 4) void wh_kernel(
    const float* __restrict__ x, const float* __restrict__ W,
    const float* __restrict__ a_src, const float* __restrict__ a_dst)
{
    __shared__ __align__(16) float x_sm[32][IN_D];      // 16 KB
    __shared__ __align__(16) float w_sm[IN_D * Oo];     // 16 KB

    const int b   = blockIdx.z;
    const int h   = blockIdx.y;
    const int n0  = blockIdx.x * 32;
    const int tid = threadIdx.x;
    const int lane = tid & 31;       // = o
    const int wq   = tid >> 5;       // warp -> 4 rows

    {   // x tile: 32*128 floats
        const float4* xg = (const float4*)(x + ((size_t)b*Nn + n0)*IN_D);
        float4* xs = (float4*)&x_sm[0][0];
        #pragma unroll
        for (int k = 0; k < 4; ++k) xs[tid + k*256] = xg[tid + k*256];
    }
    {   // W[h]: 128*32 floats
        const float4* wg = (const float4*)(W + (size_t)h*IN_D*Oo);
        float4* ws = (float4*)w_sm;
        #pragma unroll
        for (int k = 0; k < 4; ++k) ws[tid + k*256] = wg[tid + k*256];
    }
    __syncthreads();

    float acc[4] = {0.f, 0.f, 0.f, 0.f};
    #pragma unroll 8
    for (int f4 = 0; f4 < IN_D/4; ++f4) {
        float4 xv[4];
        #pragma unroll
        for (int r = 0; r < 4; ++r)
            xv[r] = ((const float4*)&x_sm[wq*4 + r][0])[f4];
        #pragma unroll
        for (int u = 0; u < 4; ++u) {
            float wv = w_sm[(f4*4 + u)*Oo + lane];
            acc[0] += (u==0?xv[0].x:u==1?xv[0].y:u==2?xv[0].z:xv[0].w) * wv;
            acc[1] += (u==0?xv[1].x:u==1?xv[1].y:u==2?xv[1].z:xv[1].w) * wv;
            acc[2] += (u==0?xv[2].x:u==1?xv[2].y:u==2?xv[2].z:xv[2].w) * wv;
            acc[3] += (u==0?xv[3].x:u==1?xv[3].y:u==2?xv[3].z:xv[3].w) * wv;
        }
    }

    const float asv = a_src[h*Oo + lane];
    const float adv = a_dst[h*Oo + lane];
    #pragma unroll
    for (int r = 0; r < 4; ++r) {
        int n = n0 + wq*4 + r;
        g_Wh[(((size_t)b*Hh + h)*Nn + n)*Oo + lane] = tf32_rn(acc[r]);
        float ps = acc[r] * asv;
        float pd = acc[r] * adv;
        #pragma unroll
        for (int s = 16; s > 0; s >>= 1) {
            ps += __shfl_xor_sync(~0u, ps, s);
            pd += __shfl_xor_sync(~0u, pd, s);
        }
        if (lane == 0) {
            g_asrc[((size_t)b*Hh + h)*Nn + n] = ps;
            g_adst[((size_t)b*Hh + h)*Nn + n] = pd;
        }
    }
}

// ============================================================================
// Kernel 2: per-(b,h) max of alpha_dst
// ============================================================================
__global__ __launch_bounds__(256) void maxd_kernel()
{
    const int bh  = blockIdx.x;
    const int tid = threadIdx.x;
    float m = -1e30f;
    for (int n = tid; n < Nn; n += 256)
        m = fmaxf(m, g_adst[(size_t)bh*Nn + n]);
    __shared__ float red[256];
    red[tid] = m;
    __syncthreads();
    for (int s = 128; s > 0; s >>= 1) {
        if (tid < s) red[tid] = fmaxf(red[tid], red[tid + s]);
        __syncthreads();
    }
    if (tid == 0) g_maxd[bh] = red[0];
}

// ============================================================================
// Kernel 3: fused masked-softmax + AV via mma.sync.m16n8k8.tf32
// grid (Nn/BI=32, Bb=4) = 128 CTAs; 512 threads (16 warps, 4/SMSP).
// Warp w: head hm = w>>1, row-half mh = w&1 (32 rows each).
// p-gen: thread -> row ith = tid>>3, j-pair j8 = tid&7.
// SMEM (dynamic, 86016 B):
//   p_sm  [8][64][20]     words 0..10239
//   wh_sm [2][8][16][40]  words 10240..20479  (cp.async double buffer)
//   ej_sm [2][8][16][2]   words 20480..20991
//   z_sm  [8][64]         words 20992..21503
// ============================================================================
__global__ __launch_bounds__(512, 1) void gat_mma(const float* __restrict__ adj,
                                                  float* __restrict__ out)
{
    extern __shared__ float sm[];
    float* p_sm  = sm;
    float* wh_sm = sm + 10240;
    float* ej_sm = sm + 20480;
    float* z_sm  = sm + 20992;

    const int tid  = threadIdx.x;
    const int lane = tid & 31;
    const int wid  = tid >> 5;       // 0..15
    const int hm   = wid >> 1;       // mma head
    const int mh   = wid & 1;        // row half (0: rows 0-31, 1: rows 32-63)
    const int b    = blockIdx.y;
    const int i0   = blockIdx.x * BI;
    const int ith  = tid >> 3;       // p-gen row 0..63
    const int j8   = tid & 7;        // p-gen j-pair (j = 2*j8, 2*j8+1)
    const int iglob = i0 + ith;
    const int g  = lane >> 2;
    const int t4 = lane & 3;

    const uint32_t wh_u32 =
        (uint32_t)__cvta_generic_to_shared(wh_sm);

    // per-(h,i) hoisted exponentials: w = max(E1i*E1j, E2i*E2j) * mask
    float E1i[Hh], E2i[Hh], zacc[Hh];
    #pragma unroll
    for (int h = 0; h < Hh; ++h) {
        float s  = g_asrc[((size_t)(b*Hh + h))*Nn + iglob];
        float md = g_maxd[b*Hh + h];
        float t  = s + md;
        float m  = fmaxf(t, 0.2f*t);                 // lrelu monotone -> row max
        E1i[h] = ex2f_fast((s - m)*LOG2E);
        E2i[h] = ex2f_fast((0.2f*s - m)*LOG2E);
        zacc[h] = 0.f;
    }

    const float2* arow  = (const float2*)(adj + ((size_t)b*Nn + iglob)*Nn);
    const float*  whg   = g_Wh + (size_t)b*Hh*Nn*Oo;
    const float*  adstb = g_adst + (size_t)b*Hh*Nn;

    // ---- prologue: cp.async wh chunk 0 -> buf 0; ej chunk 0; adj chunk 0 ----
    #pragma unroll
    for (int r = 0; r < 2; ++r) {
        int q = tid + r*512;                 // 0..1023
        int h = q >> 7, k = (q >> 3) & 15, ng = q & 7;
        cp_async16(wh_u32 + (uint32_t)(h*640 + k*40 + ng*4)*4u,
                   whg + ((size_t)h*Nn + k)*Oo + ng*4);
    }
    asm volatile("cp.async.commit_group;" ::: "memory");

    if (tid < 128) {
        int h = tid >> 4, j = tid & 15;
        float dl = adstb[(size_t)h*Nn + j] * LOG2E;
        ej_sm[h*32 + j*2 + 0] = ex2f_fast(dl);
        ej_sm[h*32 + j*2 + 1] = ex2f_fast(0.2f*dl);
    }
    float2 adjv = arow[j8];

    float acc[2][4][4];
    #pragma unroll
    for (int m = 0; m < 2; ++m)
        #pragma unroll
        for (int nt = 0; nt < 4; ++nt)
            #pragma unroll
            for (int r = 0; r < 4; ++r) acc[m][nt][r] = 0.f;

    __syncthreads();    // ej_sm[0] visible

    for (int c = 0; c < NCH; ++c) {
        const int buf = c & 1;

        // ---- issue cp.async for chunk c+1 into buf^1 ----
        if (c + 1 < NCH) {
            #pragma unroll
            for (int r = 0; r < 2; ++r) {
                int q = tid + r*512;
                int h = q >> 7, k = (q >> 3) & 15, ng = q & 7;
                cp_async16(wh_u32 + (uint32_t)((buf^1)*5120 + h*640 + k*40 + ng*4)*4u,
                           whg + ((size_t)h*Nn + (c+1)*KC + k)*Oo + ng*4);
            }
            asm volatile("cp.async.commit_group;" ::: "memory");
        }
        // ---- ej prefetch (c+1) into regs ----
        float e1n = 0.f, e2n = 0.f;
        if (c + 1 < NCH && tid < 128) {
            int h = tid >> 4, j = tid & 15;
            float dl = adstb[(size_t)h*Nn + (c+1)*KC + j] * LOG2E;
            e1n = ex2f_fast(dl);
            e2n = ex2f_fast(0.2f*dl);
        }

        // ---- mask (shared across heads) ----
        const int jb = c*KC + j8*2;
        const float m0 = (adjv.x > 0.f || jb     == iglob) ? 1.f : 0.f;
        const float m1 = (adjv.y > 0.f || jb + 1 == iglob) ? 1.f : 0.f;

        // ---- p-gen: 8 heads x 2 j ----
        #pragma unroll
        for (int h = 0; h < Hh; ++h) {
            float4 e = *(const float4*)(ej_sm + buf*256 + h*32 + j8*4);
            float w0 = fmaxf(E1i[h]*e.x, E2i[h]*e.y) * m0;
            float w1 = fmaxf(E1i[h]*e.z, E2i[h]*e.w) * m1;
            w0 = tf32_rn(w0);
            w1 = tf32_rn(w1);
            zacc[h] += w0 + w1;
            *(float2*)(p_sm + h*1280 + ith*20 + j8*2) = make_float2(w0, w1);
        }

        // ---- wait for wh[buf] ----
        if (c + 1 < NCH) asm volatile("cp.async.wait_group 1;" ::: "memory");
        else             asm volatile("cp.async.wait_group 0;" ::: "memory");
        __syncthreads();          // p ready; wh[buf] ready

        // ---- mma: warp (hm, mh) ----
        {
            const float* ph = p_sm + hm*1280 + mh*640;
            const float* wt = wh_sm + buf*5120 + hm*640;
            #pragma unroll
            for (int ks = 0; ks < 2; ++ks) {
                const int k0 = ks*8;
                uint32_t bf[4][2];
                #pragma unroll
                for (int nt = 0; nt < 4; ++nt) {
                    bf[nt][0] = __float_as_uint(wt[(k0 + t4)*40 + nt*8 + g]);
                    bf[nt][1] = __float_as_uint(wt[(k0 + t4 + 4)*40 + nt*8 + g]);
                }
                #pragma unroll
                for (int m = 0; m < 2; ++m) {
                    const float* pa = ph + (m*16 + g)*20 + k0;
                    uint32_t a0 = __float_as_uint(pa[t4]);
                    uint32_t a1 = __float_as_uint(pa[160 + t4]);
                    uint32_t a2 = __float_as_uint(pa[t4 + 4]);
                    uint32_t a3 = __float_as_uint(pa[160 + t4 + 4]);
                    #pragma unroll
                    for (int nt = 0; nt < 4; ++nt) {
                        asm volatile(
                          "mma.sync.aligned.m16n8k8.row.col.f32.tf32.tf32.f32 "
                          "{%0,%1,%2,%3}, {%4,%5,%6,%7}, {%8,%9}, {%0,%1,%2,%3};"
                          : "+f"(acc[m][nt][0]), "+f"(acc[m][nt][1]),
                            "+f"(acc[m][nt][2]), "+f"(acc[m][nt][3])
                          : "r"(a0), "r"(a1), "r"(a2), "r"(a3),
                            "r"(bf[nt][0]), "r"(bf[nt][1]));
                    }
                }
            }
        }

        // ---- prefetch adj (c+1); stage ej (c+1) ----
        if (c + 1 < NCH) {
            adjv = arow[(c+1)*8 + j8];
            if (tid < 128) {
                int h = tid >> 4, j = tid & 15;
                ej_sm[(buf^1)*256 + h*32 + j*2 + 0] = e1n;
                ej_sm[(buf^1)*256 + h*32 + j*2 + 1] = e2n;
            }
        }
        __syncthreads();          // p consumed; next ej visible
    }

    // ---- Z reduction across the 8 j8-lanes of each row ----
    #pragma unroll
    for (int h = 0; h < Hh; ++h) {
        float z = zacc[h];
        z += __shfl_xor_sync(~0u, z, 1);
        z += __shfl_xor_sync(~0u, z, 2);
        z += __shfl_xor_sync(~0u, z, 4);
        if (j8 == 0) z_sm[h*64 + ith] = z;
    }
    __syncthreads();

    // ---- epilogue: normalize, relu, store ----
    {
        float* ob = out + ((size_t)b*Nn + i0 + mh*32)*(Hh*Oo) + hm*Oo;
        #pragma unroll
        for (int m = 0; m < 2; ++m) {
            int r0 = m*16 + g;
            float zi0 = 1.f / z_sm[hm*64 + mh*32 + r0];
            float zi1 = 1.f / z_sm[hm*64 + mh*32 + r0 + 8];
            #pragma unroll
            for (int nt = 0; nt < 4; ++nt) {
                int o = nt*8 + 2*t4;
                float2 v0, v1;
                v0.x = fmaxf(acc[m][nt][0]*zi0, 0.f);
                v0.y = fmaxf(acc[m][nt][1]*zi0, 0.f);
                v1.x = fmaxf(acc[m][nt][2]*zi1, 0.f);
                v1.y = fmaxf(acc[m][nt][3]*zi1, 0.f);
                *(float2*)(ob + (size_t)r0*(Hh*Oo) + o)       = v0;
                *(float2*)(ob + (size_t)(r0 + 8)*(Hh*Oo) + o) = v1;
            }
        }
    }
}

// ============================================================================
extern "C" void kernel_launch(void* const* d_in, const int* in_sizes, int n_in,
                              void* d_out, int out_size)
{
    (void)in_sizes; (void)n_in; (void)out_size;
    const float* x     = (const float*)d_in[0];
    const float* adj   = (const float*)d_in[1];
    const float* W     = (const float*)d_in[2];
    const float* a_src = (const float*)d_in[3];
    const float* a_dst = (const float*)d_in[4];
    float* out = (float*)d_out;

    wh_kernel<<<dim3(Nn/32, Hh, Bb), 256>>>(x, W, a_src, a_dst);
    maxd_kernel<<<Bb*Hh, 256>>>();

    static const int smem_bytes = 86016;
    cudaFuncSetAttribute(gat_mma, cudaFuncAttributeMaxDynamicSharedMemorySize,
                         smem_bytes);
    gat_mma<<<dim3(Nn/BI, Bb), 512, smem_bytes>>>(adj, out);
}